// round 6
// baseline (speedup 1.0000x reference)
#include <cuda_runtime.h>
#include <math.h>

#define NPTS  32768
#define NQ    1000
#define NDATA 1024
#define NTOT  (NPTS + NQ + 2 + NDATA)   // 34794

#define THREADS 512
#define PPB 16           // 4 slots x 4 points (2 f32x2 pairs per thread)
#define GRID 152

typedef unsigned long long u64;

__device__ __forceinline__ u64 PK2(float lo, float hi) {
    u64 r; asm("mov.b64 %0, {%1, %2};" : "=l"(r) : "f"(lo), "f"(hi)); return r;
}
__device__ __forceinline__ void UPK(u64 v, float &lo, float &hi) {
    asm("mov.b64 {%0, %1}, %2;" : "=f"(lo), "=f"(hi) : "l"(v));
}
__device__ __forceinline__ void FMA2(u64 &d, u64 a, u64 b) {
    asm("fma.rn.f32x2 %0, %1, %2, %0;" : "+l"(d) : "l"(a), "l"(b));
}

// ---- device scratch ----
__device__ float g_qdd[NQ];
__device__ float g_bnd[10];
__device__ float g_pred[NDATA];
__device__ int   g_dswap;

// ============================================================
// Gauss-Legendre node i (n=1000), McMahon + Bogaert asymptotics.
// ============================================================
__device__ __forceinline__ float gl_node(int i) {
    int   k   = (i < 500) ? (i + 1) : (i - 499);
    float sgn = (i < 500) ? 0.5f : -0.5f;
    float b   = ((float)k - 0.25f) * 3.14159265358979324f;
    float ib  = 1.0f / (8.0f * b);
    float ib2 = ib * ib;
    float j0  = b + ib * (1.0f - ib2 * (41.3333333f - 8061.86667f * ib2));
    float al  = j0 * (1.0f / 1000.5f);
    float sa, ca; sincosf(al, &sa, &ca);
    float theta = al + (al * (ca / sa) - 1.0f) / (8.0f * al * 1001000.25f);
    return fmaf(sgn, cosf(theta), 0.5f);
}

// ============================================================
// data_x vs data_w disambiguation (data_x is uniform >= 0)
// ============================================================
__global__ void detect_kernel(const float* __restrict__ candA) {
    __shared__ int neg;
    if (threadIdx.x == 0) neg = 0;
    __syncthreads();
    int found = 0;
    for (int i = threadIdx.x; i < NDATA; i += blockDim.x)
        if (candA[i] < 0.0f) found = 1;
    if (found) atomicOr(&neg, 1);
    __syncthreads();
    if (threadIdx.x == 0) g_dswap = neg;
}

// ---- tanh derivative composition (Faà di Bruno, order 4) ----
__device__ __forceinline__ void fdb(float z0, float z1, float z2, float z3, float z4,
                                    float &a0, float &a1, float &a2, float &a3, float &a4) {
    float t  = tanhf(z0);
    float tt = t * t;
    float t1 = 1.0f - tt;
    float t2 = -2.0f * t * t1;
    float t3 = -2.0f * t1 * (1.0f - 3.0f * tt);
    float t4 = 8.0f * t * t1 * (2.0f - 3.0f * tt);
    float z1s = z1 * z1;
    a0 = t;
    a1 = t1 * z1;
    a2 = fmaf(t2, z1s, t1 * z2);
    a3 = fmaf(t3 * z1s, z1, fmaf(3.0f * t2 * z1, z2, t1 * z3));
    a4 = fmaf(t4 * z1s, z1s,
         fmaf(6.0f * t3 * z1s, z2,
         fmaf(t2, fmaf(3.0f * z2, z2, 4.0f * z1 * z3), t1 * z4)));
}

__device__ __forceinline__ void layer0(float s, float wj, float bj,
                                       float &a0, float &a1, float &a2, float &a3, float &a4) {
    float z  = fmaf(s, wj, bj);
    float t  = tanhf(z);
    float tt = t * t;
    float t1 = 1.0f - tt;
    float t2 = -2.0f * t * t1;
    float t3 = -2.0f * t1 * (1.0f - 3.0f * tt);
    float t4 = 8.0f * t * t1 * (2.0f - 3.0f * tt);
    float w2 = wj * wj;
    a0 = t;
    a1 = t1 * wj;
    a2 = t2 * w2;
    a3 = t3 * w2 * wj;
    a4 = t4 * w2 * w2;
}

// ============================================================
// Main kernel. 16 points per block-iteration, 4 per thread.
// Per point-pair SMEM block (1280 floats):
//   [0:256)     pt0 (ch0,ch1) pairs    [256:512)  pt0 (ch2,ch3) pairs
//   [512:768)   pt1 (ch0,ch1) pairs    [768:1024) pt1 (ch2,ch3) pairs
//   [1024:1280) (pt0.ch4, pt1.ch4) pairs
// SMEM float map:
//   sW1:0 sW2:16384 sA:32768(+8*1280) sb1:43008 sb2:43136 sW0:43264
//   sb0:43392 sW3:43520 sred:43648(+320) sb3:43968
// ============================================================
#define SMEM_FLOATS 43969

__global__ void __launch_bounds__(THREADS, 1)
pinn_main_kernel(const float* __restrict__ x,
                 const float* __restrict__ dA, const float* __restrict__ dB,
                 const float* __restrict__ W0, const float* __restrict__ b0,
                 const float* __restrict__ W1, const float* __restrict__ b1,
                 const float* __restrict__ W2, const float* __restrict__ b2,
                 const float* __restrict__ W3, const float* __restrict__ b3,
                 float* __restrict__ out, int probe)
{
    extern __shared__ float sm[];
    float* sW1  = sm;
    float* sW2  = sm + 16384;
    float* sA   = sm + 32768;
    float* sb1  = sm + 43008;
    float* sb2  = sm + 43136;
    float* sW0  = sm + 43264;
    float* sb0  = sm + 43392;
    float* sW3  = sm + 43520;
    float* sred = sm + 43648;
    float* sb3  = sm + 43968;

    int tid = threadIdx.x;
    {
        const float4* W1v = (const float4*)W1;
        const float4* W2v = (const float4*)W2;
        float4* sW1v = (float4*)sW1;
        float4* sW2v = (float4*)sW2;
        for (int idx = tid; idx < 4096; idx += THREADS) {
            sW1v[idx] = W1v[idx];
            sW2v[idx] = W2v[idx];
        }
        if (tid < 128) {
            sb1[tid] = b1[tid]; sb2[tid] = b2[tid];
            sW0[tid] = W0[tid]; sb0[tid] = b0[tid];
            sW3[tid] = W3[tid];
        }
        if (tid == 0) sb3[0] = b3[0];
    }
    __syncthreads();

    const float* dx = g_dswap ? dB : dA;

    int slot = tid >> 7;        // 0..3
    int j    = tid & 127;
    int lane = tid & 31;
    int wip  = (tid >> 5) & 3;

    float* base0 = sA + (slot * 2 + 0) * 1280;   // pair 0
    float* base1 = base0 + 1280;                 // pair 1

    const int ngroups = (NTOT + PPB - 1) / PPB;  // 2175
    const int gstep = probe ? ngroups : gridDim.x;
    for (int g = blockIdx.x; g < ngroups; g += gstep) {
        int pbase = g * PPB + slot * 4;

        auto load_s = [&](int pidx) -> float {
            float s = 0.0f;
            if (pidx < NPTS)                s = x[pidx];
            else if (pidx < NPTS + NQ)      s = gl_node(pidx - NPTS);
            else if (pidx == NPTS + NQ)     s = 0.0f;
            else if (pidx == NPTS + NQ + 1) s = 1.0f;
            else if (pidx < NTOT)           s = dx[pidx - (NPTS + NQ + 2)];
            return s;
        };

        float a0[4], a1[4], a2[4], a3[4], a4[4];
        {
            float wj = sW0[j], bj = sb0[j];
            #pragma unroll
            for (int p = 0; p < 4; ++p) {
                float s = load_s(pbase + p);
                layer0(s, wj, bj, a0[p], a1[p], a2[p], a3[p], a4[p]);
            }
        }

        #pragma unroll 1
        for (int layer = 0; layer < 2; ++layer) {
            const float* W  = layer ? sW2 : sW1;
            const float* bb = layer ? sb2 : sb1;
            __syncthreads();   // prior reads of sA done
            // stores: pair0 = points 0,1 ; pair1 = points 2,3
            ((float2*)(base0 +    0))[j] = make_float2(a0[0], a1[0]);
            ((float2*)(base0 +  256))[j] = make_float2(a2[0], a3[0]);
            ((float2*)(base0 +  512))[j] = make_float2(a0[1], a1[1]);
            ((float2*)(base0 +  768))[j] = make_float2(a2[1], a3[1]);
            ((float2*)(base0 + 1024))[j] = make_float2(a4[0], a4[1]);
            ((float2*)(base1 +    0))[j] = make_float2(a0[2], a1[2]);
            ((float2*)(base1 +  256))[j] = make_float2(a2[2], a3[2]);
            ((float2*)(base1 +  512))[j] = make_float2(a0[3], a1[3]);
            ((float2*)(base1 +  768))[j] = make_float2(a2[3], a3[3]);
            ((float2*)(base1 + 1024))[j] = make_float2(a4[2], a4[3]);
            __syncthreads();

            u64 biasv = PK2(bb[j], 0.0f);
            u64 p01A = biasv, p23A = 0ull, p01B = biasv, p23B = 0ull, p4 = 0ull;
            u64 q01A = biasv, q23A = 0ull, q01B = biasv, q23B = 0ull, q4 = 0ull;

            const ulonglong2* P01A = (const ulonglong2*)(base0);
            const ulonglong2* P23A = (const ulonglong2*)(base0 + 256);
            const ulonglong2* P01B = (const ulonglong2*)(base0 + 512);
            const ulonglong2* P23B = (const ulonglong2*)(base0 + 768);
            const ulonglong2* P4   = (const ulonglong2*)(base0 + 1024);
            const ulonglong2* Q01A = (const ulonglong2*)(base1);
            const ulonglong2* Q23A = (const ulonglong2*)(base1 + 256);
            const ulonglong2* Q01B = (const ulonglong2*)(base1 + 512);
            const ulonglong2* Q23B = (const ulonglong2*)(base1 + 768);
            const ulonglong2* Q4   = (const ulonglong2*)(base1 + 1024);

            #pragma unroll 2
            for (int i4 = 0; i4 < 32; ++i4) {
                const float* wp = W + (i4 << 9) + j;
                float w_0 = wp[0], w_1 = wp[128], w_2 = wp[256], w_3 = wp[384];
                u64 d0 = PK2(w_0, w_0), d1 = PK2(w_1, w_1);
                u64 d2 = PK2(w_2, w_2), d3 = PK2(w_3, w_3);

                {   // pair 0
                    ulonglong2 v01a = P01A[2*i4], v01b = P01A[2*i4+1];
                    ulonglong2 v23a = P23A[2*i4], v23b = P23A[2*i4+1];
                    ulonglong2 w01a = P01B[2*i4], w01b = P01B[2*i4+1];
                    ulonglong2 w23a = P23B[2*i4], w23b = P23B[2*i4+1];
                    ulonglong2 v4a  = P4[2*i4],   v4b  = P4[2*i4+1];
                    FMA2(p01A, v01a.x, d0); FMA2(p01A, v01a.y, d1);
                    FMA2(p01A, v01b.x, d2); FMA2(p01A, v01b.y, d3);
                    FMA2(p23A, v23a.x, d0); FMA2(p23A, v23a.y, d1);
                    FMA2(p23A, v23b.x, d2); FMA2(p23A, v23b.y, d3);
                    FMA2(p01B, w01a.x, d0); FMA2(p01B, w01a.y, d1);
                    FMA2(p01B, w01b.x, d2); FMA2(p01B, w01b.y, d3);
                    FMA2(p23B, w23a.x, d0); FMA2(p23B, w23a.y, d1);
                    FMA2(p23B, w23b.x, d2); FMA2(p23B, w23b.y, d3);
                    FMA2(p4,   v4a.x,  d0); FMA2(p4,   v4a.y,  d1);
                    FMA2(p4,   v4b.x,  d2); FMA2(p4,   v4b.y,  d3);
                }
                {   // pair 1
                    ulonglong2 v01a = Q01A[2*i4], v01b = Q01A[2*i4+1];
                    ulonglong2 v23a = Q23A[2*i4], v23b = Q23A[2*i4+1];
                    ulonglong2 w01a = Q01B[2*i4], w01b = Q01B[2*i4+1];
                    ulonglong2 w23a = Q23B[2*i4], w23b = Q23B[2*i4+1];
                    ulonglong2 v4a  = Q4[2*i4],   v4b  = Q4[2*i4+1];
                    FMA2(q01A, v01a.x, d0); FMA2(q01A, v01a.y, d1);
                    FMA2(q01A, v01b.x, d2); FMA2(q01A, v01b.y, d3);
                    FMA2(q23A, v23a.x, d0); FMA2(q23A, v23a.y, d1);
                    FMA2(q23A, v23b.x, d2); FMA2(q23A, v23b.y, d3);
                    FMA2(q01B, w01a.x, d0); FMA2(q01B, w01a.y, d1);
                    FMA2(q01B, w01b.x, d2); FMA2(q01B, w01b.y, d3);
                    FMA2(q23B, w23a.x, d0); FMA2(q23B, w23a.y, d1);
                    FMA2(q23B, w23b.x, d2); FMA2(q23B, w23b.y, d3);
                    FMA2(q4,   v4a.x,  d0); FMA2(q4,   v4a.y,  d1);
                    FMA2(q4,   v4b.x,  d2); FMA2(q4,   v4b.y,  d3);
                }
            }

            float z0, z1, z2, z3, z4a, z4b;
            UPK(p01A, z0, z1); UPK(p23A, z2, z3); UPK(p4, z4a, z4b);
            fdb(z0, z1, z2, z3, z4a, a0[0], a1[0], a2[0], a3[0], a4[0]);
            UPK(p01B, z0, z1); UPK(p23B, z2, z3);
            fdb(z0, z1, z2, z3, z4b, a0[1], a1[1], a2[1], a3[1], a4[1]);
            UPK(q01A, z0, z1); UPK(q23A, z2, z3); UPK(q4, z4a, z4b);
            fdb(z0, z1, z2, z3, z4a, a0[2], a1[2], a2[2], a3[2], a4[2]);
            UPK(q01B, z0, z1); UPK(q23B, z2, z3);
            fdb(z0, z1, z2, z3, z4b, a0[3], a1[3], a2[3], a3[3], a4[3]);
        }

        // ---- head: dot with W3 + warp reduce (20 channels) ----
        float w3j = sW3[j];
        float h[20];
        #pragma unroll
        for (int p = 0; p < 4; ++p) {
            h[p*5+0] = a0[p] * w3j; h[p*5+1] = a1[p] * w3j; h[p*5+2] = a2[p] * w3j;
            h[p*5+3] = a3[p] * w3j; h[p*5+4] = a4[p] * w3j;
        }
        #pragma unroll
        for (int o = 16; o; o >>= 1) {
            #pragma unroll
            for (int c = 0; c < 20; ++c)
                h[c] += __shfl_xor_sync(0xffffffffu, h[c], o);
        }
        if (lane == 0) {
            float* r = sred + (slot * 4 + wip) * 20;
            #pragma unroll
            for (int c = 0; c < 20; ++c) r[c] = h[c];
        }
        __syncthreads();
        if ((tid & 127) == 0) {
            const float* rb = sred + slot * 80;
            float bias = sb3[0];
            #pragma unroll
            for (int p = 0; p < 4; ++p) {
                int pidx = pbase + p;
                if (pidx >= NTOT) break;
                const float* r = rb + p * 5;
                float u0 = r[0] + r[20] + r[40] + r[60] + bias;
                float u1 = r[1] + r[21] + r[41] + r[61];
                float u2 = r[2] + r[22] + r[42] + r[62];
                float u3 = r[3] + r[23] + r[43] + r[63];
                float u4 = r[4] + r[24] + r[44] + r[64];
                if (pidx < NPTS) {
                    out[pidx]            = 1.5f * u0;
                    out[NPTS     + pidx] = 1.5f * u1;
                    out[2 * NPTS + pidx] = -u2;
                    out[3 * NPTS + pidx] = -u3;
                    out[4 * NPTS + pidx] = 1.5f * u4;
                } else if (pidx < NPTS + NQ) {
                    g_qdd[pidx - NPTS] = u2;
                } else if (pidx == NPTS + NQ) {
                    g_bnd[0] = u0; g_bnd[1] = u1; g_bnd[2] = u2; g_bnd[3] = u3; g_bnd[4] = u4;
                } else if (pidx == NPTS + NQ + 1) {
                    g_bnd[5] = u0; g_bnd[6] = u1; g_bnd[7] = u2; g_bnd[8] = u3; g_bnd[9] = u4;
                } else {
                    g_pred[pidx - (NPTS + NQ + 2)] = u0;
                }
            }
        }
        __syncthreads();
    }
}

// ============================================================
// Final scalar loss.
// ============================================================
__global__ void finalize_kernel(const float* __restrict__ dA,
                                const float* __restrict__ dB,
                                float* __restrict__ out)
{
    const float* dwp = g_dswap ? dA : dB;
    __shared__ float sh[1024];
    __shared__ float s_fsq;
    int tid = threadIdx.x;

    float v = 0.0f;
    if (tid < NQ) { float f = g_qdd[tid]; v = f * f; }
    sh[tid] = v; __syncthreads();
    for (int o = 512; o; o >>= 1) { if (tid < o) sh[tid] += sh[tid + o]; __syncthreads(); }
    if (tid == 0) s_fsq = sh[0];
    __syncthreads();

    float d = 0.0f;
    if (tid < NDATA) {
        float e = g_pred[tid] - dwp[tid] * (1.0f / 1.5f);
        d = e * e;
    }
    sh[tid] = d; __syncthreads();
    for (int o = 512; o; o >>= 1) { if (tid < o) sh[tid] += sh[tid + o]; __syncthreads(); }

    if (tid == 0) {
        float sum_data = sh[0] * (1.0f / (float)NDATA);
        float w0_  = g_bnd[0], dw0 = g_bnd[1];
        float wL   = g_bnd[5], ddwL = g_bnd[7], dddwL = g_bnd[8];
        float quad    = 2.0f * s_fsq;
        float inter   = 0.375f * quad;
        float exter   = 7.5f * wL;
        float res_pel = inter - exter;
        float res_dir = 0.5f * (w0_ * w0_ + dw0 * dw0);
        float Fb  = -dddwL;
        float e1  = Fb * 0.2f - 1.0f;
        float res_neu = 0.5f * (e1 * e1 + ddwL * ddwL);
        out[5 * NPTS] = res_pel + 0.5f * (res_dir + res_neu) + sum_data;
    }
}

// ============================================================
// Launch
// ============================================================
extern "C" void kernel_launch(void* const* d_in, const int* in_sizes, int n_in,
                              void* d_out, int out_size)
{
    const float *x, *dA, *dB, *W0, *b0, *W1, *b1, *W2, *b2, *W3, *b3;
    auto F = [&](int i) { return (const float*)d_in[i]; };

    if (in_sizes[0] == NPTS) {
        x = F(0); dA = F(1); dB = F(2);
        W0 = F(3); b0 = F(4); W1 = F(5); b1 = F(6);
        W2 = F(7); b2 = F(8); W3 = F(9); b3 = F(10);
    } else if (in_sizes[1] == 128) {
        W0 = F(0); b0 = F(1); W1 = F(2); b1 = F(3);
        W2 = F(4); b2 = F(5); W3 = F(6); b3 = F(7);
        x = F(8); dA = F(9); dB = F(10);
    } else {
        W0 = F(0); W1 = F(1); W2 = F(2); W3 = F(3);
        b0 = F(4); b1 = F(5); b2 = F(6); b3 = F(7);
        dA = F(8); dB = F(9); x = F(10);
    }
    float* out = (float*)d_out;

    detect_kernel<<<1, 256>>>(dA);

    size_t smem = SMEM_FLOATS * sizeof(float);
    cudaFuncSetAttribute(pinn_main_kernel,
                         cudaFuncAttributeMaxDynamicSharedMemorySize, (int)smem);
    pinn_main_kernel<<<GRID, THREADS, smem>>>(x, dA, dB, W0, b0, W1, b1, W2, b2, W3, b3, out, 0);

    finalize_kernel<<<1, 1024>>>(dA, dB, out);

    // Probe: last graph node — each block redundantly recomputes its first
    // group (idempotent, identical values) so ncu's capture lands on the
    // real kernel and gives us SASS + stall data at ~13us cost.
    pinn_main_kernel<<<GRID, THREADS, smem>>>(x, dA, dB, W0, b0, W1, b1, W2, b2, W3, b3, out, 1);
}

// round 10
// speedup vs baseline: 1.5136x; 1.5136x over previous
#include <cuda_runtime.h>
#include <math.h>

#define NPTS  32768
#define NQ    1000
#define NDATA 1024
#define NTOT  (NPTS + NQ + 2 + NDATA)   // 34794

#define THREADS 512
#define PPB 16           // 8 slots x 2 points; each thread owns 2 j-columns
#define GRID 152

typedef unsigned long long u64;

__device__ __forceinline__ u64 PK2(float lo, float hi) {
    u64 r; asm("mov.b64 %0, {%1, %2};" : "=l"(r) : "f"(lo), "f"(hi)); return r;
}
__device__ __forceinline__ void UPK(u64 v, float &lo, float &hi) {
    asm("mov.b64 {%0, %1}, %2;" : "=f"(lo), "=f"(hi) : "l"(v));
}
__device__ __forceinline__ void FMA2(u64 &d, u64 a, u64 b) {
    asm("fma.rn.f32x2 %0, %1, %2, %0;" : "+l"(d) : "l"(a), "l"(b));
}

// ---- device scratch ----
__device__ float g_qdd[NQ];
__device__ float g_bnd[10];
__device__ float g_pred[NDATA];
__device__ int   g_dswap;

// ============================================================
// Gauss-Legendre node i (n=1000), McMahon + Bogaert asymptotics.
// ============================================================
__device__ __forceinline__ float gl_node(int i) {
    int   k   = (i < 500) ? (i + 1) : (i - 499);
    float sgn = (i < 500) ? 0.5f : -0.5f;
    float b   = ((float)k - 0.25f) * 3.14159265358979324f;
    float ib  = 1.0f / (8.0f * b);
    float ib2 = ib * ib;
    float j0  = b + ib * (1.0f - ib2 * (41.3333333f - 8061.86667f * ib2));
    float al  = j0 * (1.0f / 1000.5f);
    float sa, ca; sincosf(al, &sa, &ca);
    float theta = al + (al * (ca / sa) - 1.0f) / (8.0f * al * 1001000.25f);
    return fmaf(sgn, cosf(theta), 0.5f);
}

// ============================================================
// data_x vs data_w disambiguation (data_x is uniform >= 0)
// ============================================================
__global__ void detect_kernel(const float* __restrict__ candA) {
    __shared__ int neg;
    if (threadIdx.x == 0) neg = 0;
    __syncthreads();
    int found = 0;
    for (int i = threadIdx.x; i < NDATA; i += blockDim.x)
        if (candA[i] < 0.0f) found = 1;
    if (found) atomicOr(&neg, 1);
    __syncthreads();
    if (threadIdx.x == 0) g_dswap = neg;
}

// ---- tanh derivative composition (Faà di Bruno, order 4) ----
__device__ __forceinline__ void fdb(float z0, float z1, float z2, float z3, float z4,
                                    float &a0, float &a1, float &a2, float &a3, float &a4) {
    float t  = tanhf(z0);
    float tt = t * t;
    float t1 = 1.0f - tt;
    float t2 = -2.0f * t * t1;
    float t3 = -2.0f * t1 * (1.0f - 3.0f * tt);
    float t4 = 8.0f * t * t1 * (2.0f - 3.0f * tt);
    float z1s = z1 * z1;
    a0 = t;
    a1 = t1 * z1;
    a2 = fmaf(t2, z1s, t1 * z2);
    a3 = fmaf(t3 * z1s, z1, fmaf(3.0f * t2 * z1, z2, t1 * z3));
    a4 = fmaf(t4 * z1s, z1s,
         fmaf(6.0f * t3 * z1s, z2,
         fmaf(t2, fmaf(3.0f * z2, z2, 4.0f * z1 * z3), t1 * z4)));
}

__device__ __forceinline__ void layer0(float s, float wj, float bj,
                                       float &a0, float &a1, float &a2, float &a3, float &a4) {
    float z  = fmaf(s, wj, bj);
    float t  = tanhf(z);
    float tt = t * t;
    float t1 = 1.0f - tt;
    float t2 = -2.0f * t * t1;
    float t3 = -2.0f * t1 * (1.0f - 3.0f * tt);
    float t4 = 8.0f * t * t1 * (2.0f - 3.0f * tt);
    float w2 = wj * wj;
    a0 = t;
    a1 = t1 * wj;
    a2 = t2 * w2;
    a3 = t3 * w2 * wj;
    a4 = t4 * w2 * w2;
}

// ============================================================
// Main kernel. 16 points/group: 8 slots x 64 threads x 2 points,
// each thread owns j-pair (2*jj, 2*jj+1).
// Per-slot act SMEM (1280 floats): u64[128] arrays indexed by j:
//   +0    pt0 (ch0,ch1)   +256 pt0 (ch2,ch3)
//   +512  pt1 (ch0,ch1)   +768 pt1 (ch2,ch3)
//   +1024 (pt0.ch4, pt1.ch4)
// SMEM float map: sW1:0 sW2:16384 sAct:32768(+10240) sb1:43008
//   sb2:43136 sW0:43264 sb0:43392 sW3:43520 sred:43648(+160) sb3:43808
// ============================================================
#define SMEM_FLOATS 43809

__global__ void __launch_bounds__(THREADS, 1)
pinn_main_kernel(const float* __restrict__ x,
                 const float* __restrict__ dA, const float* __restrict__ dB,
                 const float* __restrict__ W0, const float* __restrict__ b0,
                 const float* __restrict__ W1, const float* __restrict__ b1,
                 const float* __restrict__ W2, const float* __restrict__ b2,
                 const float* __restrict__ W3, const float* __restrict__ b3,
                 float* __restrict__ out)
{
    extern __shared__ float sm[];
    float* sW1  = sm;
    float* sW2  = sm + 16384;
    float* sAct = sm + 32768;
    float* sb1  = sm + 43008;
    float* sb2  = sm + 43136;
    float* sW0  = sm + 43264;
    float* sb0  = sm + 43392;
    float* sW3  = sm + 43520;
    float* sred = sm + 43648;
    float* sb3  = sm + 43808;

    int tid = threadIdx.x;
    {
        const float4* W1v = (const float4*)W1;
        const float4* W2v = (const float4*)W2;
        float4* sW1v = (float4*)sW1;
        float4* sW2v = (float4*)sW2;
        for (int idx = tid; idx < 4096; idx += THREADS) {
            sW1v[idx] = W1v[idx];
            sW2v[idx] = W2v[idx];
        }
        if (tid < 128) {
            sb1[tid] = b1[tid]; sb2[tid] = b2[tid];
            sW0[tid] = W0[tid]; sb0[tid] = b0[tid];
            sW3[tid] = W3[tid];
        }
        if (tid == 0) sb3[0] = b3[0];
    }
    __syncthreads();

    const float* dx = g_dswap ? dB : dA;

    int slot = tid >> 6;        // 0..7
    int jj   = tid & 63;        // j-pair index
    int lane = tid & 31;
    int ws   = (tid >> 5) & 1;  // warp within slot
    int j0   = jj * 2, j1 = j0 + 1;

    float* S = sAct + slot * 1280;
    ulonglong2* SP01_0 = (ulonglong2*)(S);
    ulonglong2* SP23_0 = (ulonglong2*)(S + 256);
    ulonglong2* SP01_1 = (ulonglong2*)(S + 512);
    ulonglong2* SP23_1 = (ulonglong2*)(S + 768);
    ulonglong2* SP4    = (ulonglong2*)(S + 1024);

    const int ngroups = (NTOT + PPB - 1) / PPB;  // 2175
    for (int g = blockIdx.x; g < ngroups; g += gridDim.x) {
        int pbase = g * PPB + slot * 2;

        auto load_s = [&](int pidx) -> float {
            float s = 0.0f;
            if (pidx < NPTS)                s = x[pidx];
            else if (pidx < NPTS + NQ)      s = gl_node(pidx - NPTS);
            else if (pidx == NPTS + NQ)     s = 0.0f;
            else if (pidx == NPTS + NQ + 1) s = 1.0f;
            else if (pidx < NTOT)           s = dx[pidx - (NPTS + NQ + 2)];
            return s;
        };
        float sIn[2] = { load_s(pbase), load_s(pbase + 1) };

        // a[pt][jt][ch]
        float a0[2][2], a1[2][2], a2[2][2], a3[2][2], a4[2][2];
        {
            float wA = sW0[j0], bA = sb0[j0];
            float wB = sW0[j1], bB = sb0[j1];
            #pragma unroll
            for (int pt = 0; pt < 2; ++pt) {
                layer0(sIn[pt], wA, bA, a0[pt][0], a1[pt][0], a2[pt][0], a3[pt][0], a4[pt][0]);
                layer0(sIn[pt], wB, bB, a0[pt][1], a1[pt][1], a2[pt][1], a3[pt][1], a4[pt][1]);
            }
        }

        #pragma unroll 1
        for (int layer = 0; layer < 2; ++layer) {
            const float* W  = layer ? sW2 : sW1;
            const u64*  bbp = (const u64*)(layer ? sb2 : sb1);
            __syncthreads();   // prior reads of sAct done
            {
                ulonglong2 v;
                v.x = PK2(a0[0][0], a1[0][0]); v.y = PK2(a0[0][1], a1[0][1]);
                SP01_0[jj] = v;
                v.x = PK2(a2[0][0], a3[0][0]); v.y = PK2(a2[0][1], a3[0][1]);
                SP23_0[jj] = v;
                v.x = PK2(a0[1][0], a1[1][0]); v.y = PK2(a0[1][1], a1[1][1]);
                SP01_1[jj] = v;
                v.x = PK2(a2[1][0], a3[1][0]); v.y = PK2(a2[1][1], a3[1][1]);
                SP23_1[jj] = v;
                v.x = PK2(a4[0][0], a4[1][0]); v.y = PK2(a4[0][1], a4[1][1]);
                SP4[jj] = v;
            }
            __syncthreads();

            // accumulators: A* = (x_j0 , y_j1), B* = (x_j1 , y_j0)
            float bl, bh; UPK(bbp[jj], bl, bh);
            u64 A01_0 = PK2(bl, 0.0f), B01_0 = PK2(bh, 0.0f);
            u64 A01_1 = A01_0,         B01_1 = B01_0;
            u64 A23_0 = 0ull, B23_0 = 0ull, A23_1 = 0ull, B23_1 = 0ull;
            u64 A4 = 0ull, B4 = 0ull;

            const ulonglong2* L01_0 = SP01_0;
            const ulonglong2* L23_0 = SP23_0;
            const ulonglong2* L01_1 = SP01_1;
            const ulonglong2* L23_1 = SP23_1;
            const ulonglong2* L4    = SP4;

            #pragma unroll 4
            for (int i4 = 0; i4 < 32; ++i4) {
                const u64* Wr = (const u64*)(W + (i4 << 9));
                u64 w0 = Wr[jj], w1 = Wr[64 + jj], w2 = Wr[128 + jj], w3 = Wr[192 + jj];
                float wl, wh;
                UPK(w0, wl, wh); u64 s0 = PK2(wh, wl);
                UPK(w1, wl, wh); u64 s1 = PK2(wh, wl);
                UPK(w2, wl, wh); u64 s2 = PK2(wh, wl);
                UPK(w3, wl, wh); u64 s3 = PK2(wh, wl);

                ulonglong2 p01a = L01_0[2*i4], p01b = L01_0[2*i4+1];
                ulonglong2 p23a = L23_0[2*i4], p23b = L23_0[2*i4+1];
                ulonglong2 q01a = L01_1[2*i4], q01b = L01_1[2*i4+1];
                ulonglong2 q23a = L23_1[2*i4], q23b = L23_1[2*i4+1];
                ulonglong2 v4a  = L4[2*i4],    v4b  = L4[2*i4+1];

                // input 4*i4+0
                FMA2(A01_0, p01a.x, w0); FMA2(B01_0, p01a.x, s0);
                FMA2(A23_0, p23a.x, w0); FMA2(B23_0, p23a.x, s0);
                FMA2(A01_1, q01a.x, w0); FMA2(B01_1, q01a.x, s0);
                FMA2(A23_1, q23a.x, w0); FMA2(B23_1, q23a.x, s0);
                FMA2(A4,    v4a.x,  w0); FMA2(B4,    v4a.x,  s0);
                // input 4*i4+1
                FMA2(A01_0, p01a.y, w1); FMA2(B01_0, p01a.y, s1);
                FMA2(A23_0, p23a.y, w1); FMA2(B23_0, p23a.y, s1);
                FMA2(A01_1, q01a.y, w1); FMA2(B01_1, q01a.y, s1);
                FMA2(A23_1, q23a.y, w1); FMA2(B23_1, q23a.y, s1);
                FMA2(A4,    v4a.y,  w1); FMA2(B4,    v4a.y,  s1);
                // input 4*i4+2
                FMA2(A01_0, p01b.x, w2); FMA2(B01_0, p01b.x, s2);
                FMA2(A23_0, p23b.x, w2); FMA2(B23_0, p23b.x, s2);
                FMA2(A01_1, q01b.x, w2); FMA2(B01_1, q01b.x, s2);
                FMA2(A23_1, q23b.x, w2); FMA2(B23_1, q23b.x, s2);
                FMA2(A4,    v4b.x,  w2); FMA2(B4,    v4b.x,  s2);
                // input 4*i4+3
                FMA2(A01_0, p01b.y, w3); FMA2(B01_0, p01b.y, s3);
                FMA2(A23_0, p23b.y, w3); FMA2(B23_0, p23b.y, s3);
                FMA2(A01_1, q01b.y, w3); FMA2(B01_1, q01b.y, s3);
                FMA2(A23_1, q23b.y, w3); FMA2(B23_1, q23b.y, s3);
                FMA2(A4,    v4b.y,  w3); FMA2(B4,    v4b.y,  s3);
            }

            // unpack: A = (x_j0, y_j1), B = (x_j1, y_j0)
            float z0a, z0b, z1a, z1b, z2a, z2b, z3a, z3b;
            float z4_00, z4_01, z4_10, z4_11;
            UPK(A4, z4_00, z4_11);   // (pt0 j0, pt1 j1)
            UPK(B4, z4_01, z4_10);   // (pt0 j1, pt1 j0)

            UPK(A01_0, z0a, z1b); UPK(B01_0, z0b, z1a);
            UPK(A23_0, z2a, z3b); UPK(B23_0, z2b, z3a);
            fdb(z0a, z1a, z2a, z3a, z4_00, a0[0][0], a1[0][0], a2[0][0], a3[0][0], a4[0][0]);
            fdb(z0b, z1b, z2b, z3b, z4_01, a0[0][1], a1[0][1], a2[0][1], a3[0][1], a4[0][1]);

            UPK(A01_1, z0a, z1b); UPK(B01_1, z0b, z1a);
            UPK(A23_1, z2a, z3b); UPK(B23_1, z2b, z3a);
            fdb(z0a, z1a, z2a, z3a, z4_10, a0[1][0], a1[1][0], a2[1][0], a3[1][0], a4[1][0]);
            fdb(z0b, z1b, z2b, z3b, z4_11, a0[1][1], a1[1][1], a2[1][1], a3[1][1], a4[1][1]);
        }

        // ---- head: dot with W3 + reduce over 128 j (2 per thread, 2 warps) ----
        float w3a = sW3[j0], w3b = sW3[j1];
        float h[10];
        #pragma unroll
        for (int pt = 0; pt < 2; ++pt) {
            h[pt*5+0] = fmaf(a0[pt][0], w3a, a0[pt][1] * w3b);
            h[pt*5+1] = fmaf(a1[pt][0], w3a, a1[pt][1] * w3b);
            h[pt*5+2] = fmaf(a2[pt][0], w3a, a2[pt][1] * w3b);
            h[pt*5+3] = fmaf(a3[pt][0], w3a, a3[pt][1] * w3b);
            h[pt*5+4] = fmaf(a4[pt][0], w3a, a4[pt][1] * w3b);
        }
        #pragma unroll
        for (int o = 16; o; o >>= 1) {
            #pragma unroll
            for (int c = 0; c < 10; ++c)
                h[c] += __shfl_xor_sync(0xffffffffu, h[c], o);
        }
        if (lane == 0) {
            float* r = sred + (slot * 2 + ws) * 10;
            #pragma unroll
            for (int c = 0; c < 10; ++c) r[c] = h[c];
        }
        __syncthreads();
        if (jj == 0) {
            const float* r = sred + slot * 20;
            float bias = sb3[0];
            #pragma unroll
            for (int pt = 0; pt < 2; ++pt) {
                int pidx = pbase + pt;
                if (pidx >= NTOT) break;
                float u0 = r[pt*5+0] + r[10+pt*5+0] + bias;
                float u1 = r[pt*5+1] + r[10+pt*5+1];
                float u2 = r[pt*5+2] + r[10+pt*5+2];
                float u3 = r[pt*5+3] + r[10+pt*5+3];
                float u4 = r[pt*5+4] + r[10+pt*5+4];
                if (pidx < NPTS) {
                    out[pidx]            = 1.5f * u0;
                    out[NPTS     + pidx] = 1.5f * u1;
                    out[2 * NPTS + pidx] = -u2;
                    out[3 * NPTS + pidx] = -u3;
                    out[4 * NPTS + pidx] = 1.5f * u4;
                } else if (pidx < NPTS + NQ) {
                    g_qdd[pidx - NPTS] = u2;
                } else if (pidx == NPTS + NQ) {
                    g_bnd[0] = u0; g_bnd[1] = u1; g_bnd[2] = u2; g_bnd[3] = u3; g_bnd[4] = u4;
                } else if (pidx == NPTS + NQ + 1) {
                    g_bnd[5] = u0; g_bnd[6] = u1; g_bnd[7] = u2; g_bnd[8] = u3; g_bnd[9] = u4;
                } else {
                    g_pred[pidx - (NPTS + NQ + 2)] = u0;
                }
            }
        }
        __syncthreads();
    }
}

// ============================================================
// Final scalar loss.
// ============================================================
__global__ void finalize_kernel(const float* __restrict__ dA,
                                const float* __restrict__ dB,
                                float* __restrict__ out)
{
    const float* dwp = g_dswap ? dA : dB;
    __shared__ float sh[1024];
    __shared__ float s_fsq;
    int tid = threadIdx.x;

    float v = 0.0f;
    if (tid < NQ) { float f = g_qdd[tid]; v = f * f; }
    sh[tid] = v; __syncthreads();
    for (int o = 512; o; o >>= 1) { if (tid < o) sh[tid] += sh[tid + o]; __syncthreads(); }
    if (tid == 0) s_fsq = sh[0];
    __syncthreads();

    float d = 0.0f;
    if (tid < NDATA) {
        float e = g_pred[tid] - dwp[tid] * (1.0f / 1.5f);
        d = e * e;
    }
    sh[tid] = d; __syncthreads();
    for (int o = 512; o; o >>= 1) { if (tid < o) sh[tid] += sh[tid + o]; __syncthreads(); }

    if (tid == 0) {
        float sum_data = sh[0] * (1.0f / (float)NDATA);
        float w0_  = g_bnd[0], dw0 = g_bnd[1];
        float wL   = g_bnd[5], ddwL = g_bnd[7], dddwL = g_bnd[8];
        float quad    = 2.0f * s_fsq;
        float inter   = 0.375f * quad;
        float exter   = 7.5f * wL;
        float res_pel = inter - exter;
        float res_dir = 0.5f * (w0_ * w0_ + dw0 * dw0);
        float Fb  = -dddwL;
        float e1  = Fb * 0.2f - 1.0f;
        float res_neu = 0.5f * (e1 * e1 + ddwL * ddwL);
        out[5 * NPTS] = res_pel + 0.5f * (res_dir + res_neu) + sum_data;
    }
}

// ============================================================
// Launch
// ============================================================
extern "C" void kernel_launch(void* const* d_in, const int* in_sizes, int n_in,
                              void* d_out, int out_size)
{
    const float *x, *dA, *dB, *W0, *b0, *W1, *b1, *W2, *b2, *W3, *b3;
    auto F = [&](int i) { return (const float*)d_in[i]; };

    if (in_sizes[0] == NPTS) {
        x = F(0); dA = F(1); dB = F(2);
        W0 = F(3); b0 = F(4); W1 = F(5); b1 = F(6);
        W2 = F(7); b2 = F(8); W3 = F(9); b3 = F(10);
    } else if (in_sizes[1] == 128) {
        W0 = F(0); b0 = F(1); W1 = F(2); b1 = F(3);
        W2 = F(4); b2 = F(5); W3 = F(6); b3 = F(7);
        x = F(8); dA = F(9); dB = F(10);
    } else {
        W0 = F(0); W1 = F(1); W2 = F(2); W3 = F(3);
        b0 = F(4); b1 = F(5); b2 = F(6); b3 = F(7);
        dA = F(8); dB = F(9); x = F(10);
    }
    float* out = (float*)d_out;

    detect_kernel<<<1, 256>>>(dA);

    size_t smem = SMEM_FLOATS * sizeof(float);
    cudaFuncSetAttribute(pinn_main_kernel,
                         cudaFuncAttributeMaxDynamicSharedMemorySize, (int)smem);
    pinn_main_kernel<<<GRID, THREADS, smem>>>(x, dA, dB, W0, b0, W1, b1, W2, b2, W3, b3, out);

    finalize_kernel<<<1, 1024>>>(dA, dB, out);
}